// round 2
// baseline (speedup 1.0000x reference)
#include <cuda_runtime.h>
#include <cuda_bf16.h>

#define DIM 256
#define H   4
#define DK  64
#define TA  16
#define TB  32
#define NMAX 4096

// Scratch (no cudaMalloc allowed): Q,K,V projections, 4 MB each.
__device__ float g_Q[NMAX * DIM];
__device__ float g_K[NMAX * DIM];
__device__ float g_V[NMAX * DIM];
__device__ int   g_mask_flags;   // zero-initialized; atomicOr only (idempotent across graph replays)

__device__ __forceinline__ float san(float x) {
    if (isnan(x)) return 0.0f;
    if (isinf(x)) return x > 0.0f ? 1.0f : -1.0f;
    return x;
}

// ---------------------------------------------------------------------------
// Mask dtype detection (bool serialized as int32/f32/bf16/u8 -> detect).
// ---------------------------------------------------------------------------
__global__ void detect_mask_kernel(const unsigned int* __restrict__ m, int nwords) {
    int flags = 0;
    for (int i = threadIdx.x + blockIdx.x * blockDim.x; i < nwords;
         i += blockDim.x * gridDim.x) {
        unsigned int w = m[i];
        if (w > 1u) flags |= 1;
        if (w != 0u && w != 0x3F800000u) flags |= 2;
        unsigned int lo = w & 0xFFFFu, hi = w >> 16;
        if ((lo != 0u && lo != 0x3F80u) || (hi != 0u && hi != 0x3F80u)) flags |= 4;
    }
    if (flags) atomicOr(&g_mask_flags, flags);
}

__device__ __forceinline__ int mask_read(const void* m, long i, int mode) {
    switch (mode) {
        case 0:  return ((const int*)m)[i] != 0;
        case 1:  return ((const float*)m)[i] != 0.0f;
        case 2:  return ((const unsigned short*)m)[i] != 0;
        default: return ((const unsigned char*)m)[i] != 0;
    }
}

// ---------------------------------------------------------------------------
// Projection GEMMs: C = X @ W^T. blockIdx.z selects (Q,K,V).
// ---------------------------------------------------------------------------
__global__ __launch_bounds__(256) void proj_kernel(
    const float* __restrict__ a_z, const float* __restrict__ bv_z,
    const float* __restrict__ Wq, const float* __restrict__ Wk,
    const float* __restrict__ Wv, int Na, int Nb)
{
    __shared__ float As[64][17];
    __shared__ float Bs[64][17];

    int sel = blockIdx.z;
    const float* X = (sel == 0) ? a_z : bv_z;
    const float* W = (sel == 0) ? Wq : (sel == 1 ? Wk : Wv);
    float*       C = (sel == 0) ? g_Q : (sel == 1 ? g_K : g_V);
    int M = (sel == 0) ? Na : Nb;

    int mbase = blockIdx.x * 64;
    int nbase = blockIdx.y * 64;
    if (mbase >= M) return;

    int t  = threadIdx.x;
    int tm = t >> 4, tn = t & 15;

    float acc[4][4] = {};

    for (int kb = 0; kb < DIM; kb += 16) {
        #pragma unroll
        for (int r = 0; r < 4; r++) {
            int i = t + r * 256;
            int m = i >> 4, k = i & 15;
            int gm = mbase + m;
            float xv = (gm < M) ? X[(long)gm * DIM + kb + k] : 0.0f;
            As[m][k] = san(xv);
            Bs[m][k] = W[(long)(nbase + m) * DIM + kb + k];
        }
        __syncthreads();
        #pragma unroll
        for (int k = 0; k < 16; k++) {
            float af[4], bf[4];
            #pragma unroll
            for (int i = 0; i < 4; i++) af[i] = As[tm * 4 + i][k];
            #pragma unroll
            for (int j = 0; j < 4; j++) bf[j] = Bs[tn * 4 + j][k];
            #pragma unroll
            for (int i = 0; i < 4; i++)
                #pragma unroll
                for (int j = 0; j < 4; j++) acc[i][j] += af[i] * bf[j];
        }
        __syncthreads();
    }
    #pragma unroll
    for (int i = 0; i < 4; i++) {
        int gm = mbase + tm * 4 + i;
        if (gm < M) {
            #pragma unroll
            for (int j = 0; j < 4; j++)
                C[(long)gm * DIM + nbase + tn * 4 + j] = acc[i][j];
        }
    }
}

// ---------------------------------------------------------------------------
// Fused attention. One block = TA(16) a-rows. 4 warps = 4 heads.
// Streaming softmax w/o max-subtract (scores clipped to [-10,10]).
// K stored natural [b][c] with odd row pad 257 -> conflict-free scalar access.
// V stored natural [b][c] unpadded -> aligned float4 row-internal access.
// ---------------------------------------------------------------------------
// Shared layout (floats):
//   Qs  [256][20]  = 5120   (Q tile, transposed [c][a], pad 20 for float4)
//   KV  32*257     = 8224   (K padded-natural, then V unpadded-natural)
//   E   [4][32][16]= 2048   (exp scores; reused as Topic at end)
//   Bw  [16][33]   =  528
//   den [4][16]    =   64
#define QPAD   20
#define KPAD   257
#define SM_QS  0
#define SM_KV  (SM_QS + 256 * QPAD)
#define SM_E   (SM_KV + TB * KPAD)
#define SM_BW  (SM_E + 2048)
#define SM_DEN (SM_BW + 528)
#define SM_TOTAL_FLOATS (SM_DEN + 64)

__global__ __launch_bounds__(128, 3) void attn_kernel(
    const void* __restrict__ mask, const float* __restrict__ weight,
    float* __restrict__ out, int Na, int Nb)
{
    extern __shared__ float sm[];
    float* Qs    = sm + SM_QS;
    float* KV    = sm + SM_KV;
    float* E     = sm + SM_E;
    float* Bw    = sm + SM_BW;
    float* den   = sm + SM_DEN;
    float* Topic = E;   // reused after main loop (16*64 = 1024 <= 2048)

    int t    = threadIdx.x;
    int w    = t >> 5;        // head
    int l    = t & 31;
    int arow = l & 3;         // 4 groups of 4 a-rows
    int grp  = l >> 2;        // phase1: b-col group (8x4b) ; phase2: dk group (8x8)
    int abase = blockIdx.x * TA;

    int fl = g_mask_flags;
    int mmode = (!(fl & 1)) ? 0 : (!(fl & 2)) ? 1 : (!(fl & 4)) ? 2 : 3;

    // Q tile, transposed Qs[c][a] (pad QPAD; once per block)
    for (int i = t; i < TA * DIM; i += 128) {
        int a = i >> 8, c = i & 255;
        Qs[c * QPAD + a] = g_Q[(long)(abase + a) * DIM + c];
    }

    // Hoisted per-thread bases
    int krow0 = (grp * 4 + 0) * KPAD;
    int krow1 = (grp * 4 + 1) * KPAD;
    int krow2 = (grp * 4 + 2) * KPAD;
    int krow3 = (grp * 4 + 3) * KPAD;

    float ctx[4][8] = {};    // [a-frag][dk-frag], persists across tiles
    float dloc[4]   = {};    // per-a partial denominators
    __syncthreads();

    for (int bt = 0; bt < Nb; bt += TB) {
        // ---- K tile, natural [b][c], row pad KPAD (scalar STS, N<=2) ----
        for (int i = t; i < TB * DIM / 4; i += 128) {
            int b = i >> 6; int c4 = (i & 63) * 4;
            float4 kv = *(const float4*)&g_K[(long)(bt + b) * DIM + c4];
            float* dst = &KV[b * KPAD + c4];
            dst[0] = kv.x; dst[1] = kv.y; dst[2] = kv.z; dst[3] = kv.w;
        }
        // ---- bias tile: weight + (mask ? 0 : -1e4) ----
        for (int i = t; i < TA * TB; i += 128) {
            int a = i >> 5, b = i & 31;
            long gi = (long)(abase + a) * Nb + (bt + b);
            float wv = san(weight[gi]);
            int m = mask_read(mask, gi, mmode);
            Bw[a * 33 + b] = wv + (m ? 0.0f : -10000.0f);
        }
        __syncthreads();

        // ---- phase1: 16x32 score GEMM, 4x4 frag / thread ----
        // af: one broadcast LDS.128 ; bf: 4 conflict-free scalar LDS (odd stride)
        float s[4][4] = {};
        #pragma unroll 4
        for (int k = 0; k < DK; k++) {
            int c = w * DK + k;
            float4 av = *(const float4*)&Qs[c * QPAD + arow * 4];
            const float* af = (const float*)&av;
            float bf[4];
            bf[0] = KV[krow0 + c];
            bf[1] = KV[krow1 + c];
            bf[2] = KV[krow2 + c];
            bf[3] = KV[krow3 + c];
            #pragma unroll
            for (int i = 0; i < 4; i++)
                #pragma unroll
                for (int j = 0; j < 4; j++) s[i][j] += af[i] * bf[j];
        }
        // epilogue: att -> e -> smem E[w][b][a]
        #pragma unroll
        for (int j = 0; j < 4; j++) {
            int b = grp * 4 + j;
            float4 ev;
            float* ep = (float*)&ev;
            #pragma unroll
            for (int i = 0; i < 4; i++) {
                int a = arow * 4 + i;
                float bias = Bw[a * 33 + b];
                float m01  = (bias > -5000.0f) ? 1.0f : 0.0f;  // recover mask bit
                float att  = s[i][j] * 0.125f * m01 + bias;
                att = fminf(fmaxf(att, -10.0f), 10.0f);
                float e = __expf(att);
                ep[i] = e;
                dloc[i] += e;
            }
            *(float4*)&E[((w * TB) + b) * 16 + arow * 4] = ev;
        }
        __syncthreads();

        // ---- V tile, natural [b][c] UNPADDED (float4 STS, conflict-free) ----
        for (int i = t; i < TB * DIM / 4; i += 128) {
            int b = i >> 6; int c4 = (i & 63) * 4;
            *(float4*)&KV[b * DIM + c4] =
                *(const float4*)&g_V[(long)(bt + b) * DIM + c4];
        }
        __syncthreads();

        // ---- phase2: PV accumulation (4a x 8dk frag / thread) ----
        #pragma unroll 4
        for (int b = 0; b < TB; b++) {
            float4 ef = *(float4*)&E[(w * TB + b) * 16 + arow * 4];
            float* ep = (float*)&ef;
            float vf[8];
            *(float4*)&vf[0] = *(float4*)&KV[b * DIM + w * DK + grp * 8];
            *(float4*)&vf[4] = *(float4*)&KV[b * DIM + w * DK + grp * 8 + 4];
            #pragma unroll
            for (int i = 0; i < 4; i++)
                #pragma unroll
                for (int j = 0; j < 8; j++) ctx[i][j] += ep[i] * vf[j];
        }
        __syncthreads();
    }

    // Reduce denominators across the 8 b-col groups (lane bits 2..4)
    #pragma unroll
    for (int i = 0; i < 4; i++) {
        float v = dloc[i];
        v += __shfl_xor_sync(0xffffffffu, v, 4);
        v += __shfl_xor_sync(0xffffffffu, v, 8);
        v += __shfl_xor_sync(0xffffffffu, v, 16);
        dloc[i] = v;
    }
    if (grp == 0) {
        #pragma unroll
        for (int i = 0; i < 4; i++) den[w * TA + arow * 4 + i] = dloc[i];
    }
    __syncthreads();

    // Cross-head mean: Topic[a][d] = (1/4) sum_h ctx/den
    for (int i = t; i < TA * DK; i += 128) Topic[i] = 0.0f;
    __syncthreads();
    #pragma unroll
    for (int i = 0; i < 4; i++) {
        int a = arow * 4 + i;
        float inv = 0.25f / den[w * TA + a];
        #pragma unroll
        for (int j = 0; j < 8; j++)
            atomicAdd(&Topic[a * DK + grp * 8 + j], ctx[i][j] * inv);
    }
    __syncthreads();

    // Outputs: topic_align [Na,64] then influence [Na]
    for (int i = t; i < TA * DK; i += 128) {
        int a = i >> 6, dcol = i & 63;
        out[(long)(abase + a) * DK + dcol] = Topic[i];
    }
    // influence = sum_b mean_h softmax = exactly 1 per row
    if (t < TA) out[(long)Na * DK + abase + t] = 1.0f;
}

// ---------------------------------------------------------------------------
extern "C" void kernel_launch(void* const* d_in, const int* in_sizes, int n_in,
                              void* d_out, int out_size)
{
    const float* a_z    = (const float*)d_in[0];
    const float* bv_z   = (const float*)d_in[1];
    const void*  mask   = d_in[2];
    const float* weight = (const float*)d_in[3];
    const float* Wq     = (const float*)d_in[4];
    const float* Wk     = (const float*)d_in[5];
    const float* Wv     = (const float*)d_in[6];

    int Na = in_sizes[0] / DIM;
    int Nb = in_sizes[1] / DIM;
    float* out = (float*)d_out;

    int nwords = in_sizes[2] / 4;
    if (nwords > 16384) nwords = 16384;
    detect_mask_kernel<<<32, 256>>>((const unsigned int*)mask, nwords);

    int Mmax = (Na > Nb) ? Na : Nb;
    dim3 pgrid((Mmax + 63) / 64, DIM / 64, 3);
    proj_kernel<<<pgrid, 256>>>(a_z, bv_z, Wq, Wk, Wv, Na, Nb);

    size_t smem_bytes = SM_TOTAL_FLOATS * sizeof(float);
    cudaFuncSetAttribute(attn_kernel,
                         cudaFuncAttributeMaxDynamicSharedMemorySize,
                         (int)smem_bytes);
    attn_kernel<<<Na / TA, 128, smem_bytes>>>(mask, weight, out, Na, Nb);
}

// round 15
// speedup vs baseline: 2.5582x; 2.5582x over previous
#include <cuda_runtime.h>
#include <cuda_bf16.h>
#include <cstdint>

#define DIM  256
#define H    4
#define DKH  64          // per-head dim
#define BM   128         // a-rows per attn block
#define BN   64          // b tile
#define NMAX 4096

// tcgen05 exists only in arch-SPECIFIC (sm_10xa) passes. The harness build
// includes a plain compute_103/sm_103 pass (seen in R7 ptxas errors), which
// gets a register-tiled fp32 fallback body instead.
#if defined(__CUDA_ARCH_FEAT_SM103_ALL) || defined(__CUDA_ARCH_FEAT_SM100_ALL) || \
    (defined(__CUDA_ARCH_SPECIFIC__) && (__CUDA_ARCH_SPECIFIC__ >= 1000))
#define TCGEN05_OK 1
#else
#define TCGEN05_OK 0
#endif

// Scratch (no cudaMalloc allowed)
__device__ float g_Q[NMAX * DIM];
__device__ float g_K[NMAX * DIM];
__device__ float g_V[NMAX * DIM];
__device__ int   g_mask_flags;   // atomicOr only: idempotent across graph replays

__device__ __forceinline__ float san(float x) {
    if (isnan(x)) return 0.0f;
    if (isinf(x)) return x > 0.0f ? 1.0f : -1.0f;
    return x;
}

// ===========================================================================
// PTX helpers (guarded: only compiled in sm_10xa passes)
// ===========================================================================
__device__ __forceinline__ uint32_t smem_u32(const void* p) {
    uint32_t a;
    asm("{ .reg .u64 t; cvta.to.shared.u64 t, %1; cvt.u32.u64 %0, t; }" : "=r"(a) : "l"(p));
    return a;
}

#if TCGEN05_OK
__device__ __forceinline__ uint32_t elect_one() {
    uint32_t p;
    asm volatile("{\n\t.reg .pred p;\n\telect.sync _|p, 0xFFFFFFFF;\n\tselp.b32 %0, 1, 0, p;\n\t}" : "=r"(p));
    return p;
}
#define TC_ALLOC(saddr, n)  asm volatile("tcgen05.alloc.cta_group::1.sync.aligned.shared::cta.b32 [%0], %1;" :: "r"(saddr), "r"((uint32_t)(n)) : "memory")
#define TC_DEALLOC(t, n)    asm volatile("tcgen05.dealloc.cta_group::1.sync.aligned.b32 %0, %1;" :: "r"(t), "r"((uint32_t)(n)))
#define TC_RELINQ()         asm volatile("tcgen05.relinquish_alloc_permit.cta_group::1.sync.aligned;")
#define TC_COMMIT(mbar)     asm volatile("tcgen05.commit.cta_group::1.mbarrier::arrive::one.shared::cluster.b64 [%0];" :: "r"(mbar) : "memory")
#define TC_WAIT_LD()        asm volatile("tcgen05.wait::ld.sync.aligned;" ::: "memory")
#define TC_FENCE_AFTER()    asm volatile("tcgen05.fence::after_thread_sync;" ::: "memory")
#define TC_FENCE_BEFORE()   asm volatile("tcgen05.fence::before_thread_sync;" ::: "memory")
#define FENCE_ASYNC_SHARED() asm volatile("fence.proxy.async.shared::cta;" ::: "memory")
#define MBAR_INIT(a, c)     asm volatile("mbarrier.init.shared.b64 [%0], %1;" :: "r"(a), "r"((uint32_t)(c)) : "memory")

#define MBAR_WAIT(mbar, par) do {                                             \
    uint32_t _m = (mbar), _p = (par), _d;                                     \
    asm volatile("{\n\t.reg .pred p;\n\t"                                     \
        "mbarrier.try_wait.parity.acquire.cta.shared::cta.b64 p, [%1], %2;\n\t" \
        "selp.b32 %0, 1, 0, p;\n\t}" : "=r"(_d) : "r"(_m), "r"(_p) : "memory"); \
    if (!_d) {                                                                \
        asm volatile("{\n\t.reg .pred P1;\n\t"                                \
            "WL_%=:\n\t"                                                      \
            "mbarrier.try_wait.parity.acquire.cta.shared::cta.b64 P1, [%0], %1, 0x989680;\n\t" \
            "@P1 bra.uni WD_%=;\n\t"                                          \
            "bra.uni WL_%=;\n\t"                                              \
            "WD_%=:\n\t}" :: "r"(_m), "r"(_p) : "memory");                    \
    }                                                                         \
} while (0)

#define TC_LD_X32(r, addr) \
    asm volatile("tcgen05.ld.sync.aligned.32x32b.x32.b32 " \
        "{%0,%1,%2,%3,%4,%5,%6,%7,%8,%9,%10,%11,%12,%13,%14,%15," \
        "%16,%17,%18,%19,%20,%21,%22,%23,%24,%25,%26,%27,%28,%29,%30,%31}, [%32];" \
        : "=r"((r)[0]),"=r"((r)[1]),"=r"((r)[2]),"=r"((r)[3]),"=r"((r)[4]),"=r"((r)[5]),"=r"((r)[6]),"=r"((r)[7]), \
          "=r"((r)[8]),"=r"((r)[9]),"=r"((r)[10]),"=r"((r)[11]),"=r"((r)[12]),"=r"((r)[13]),"=r"((r)[14]),"=r"((r)[15]), \
          "=r"((r)[16]),"=r"((r)[17]),"=r"((r)[18]),"=r"((r)[19]),"=r"((r)[20]),"=r"((r)[21]),"=r"((r)[22]),"=r"((r)[23]), \
          "=r"((r)[24]),"=r"((r)[25]),"=r"((r)[26]),"=r"((r)[27]),"=r"((r)[28]),"=r"((r)[29]),"=r"((r)[30]),"=r"((r)[31]) \
        : "r"(addr))

// bf16 SS MMA, cta_group::1, kind::f16 (A and B from SMEM descriptors)
__device__ __forceinline__ void mma_bf16_ss(uint32_t d_tmem, uint64_t a_desc,
                                            uint64_t b_desc, uint32_t idesc, bool acc) {
    uint32_t en = acc ? 1u : 0u;
    asm volatile(
        "{\n\t.reg .pred p;\n\tsetp.ne.u32 p, %5, 0;\n\t"
        "tcgen05.mma.cta_group::1.kind::f16 [%0], %1, %2, %3, {%4, %4, %4, %4}, p;\n\t}"
        :: "r"(d_tmem), "l"(a_desc), "l"(b_desc), "r"(idesc), "r"(0u), "r"(en)
        : "memory");
}
#endif // TCGEN05_OK

// SW128 K-major descriptor (verified constants from examples)
static __device__ constexpr uint64_t DESC_BASE_SW128 =
    (uint64_t(2) << 61) | (uint64_t(1) << 46) | (uint64_t(64) << 32) | (uint64_t(1) << 16);
__device__ __forceinline__ uint64_t make_desc(uint32_t saddr) {
    return DESC_BASE_SW128 | ((uint64_t)(saddr >> 4) & 0x3FFF);
}
__device__ __forceinline__ uint32_t swz(uint32_t off) { return off ^ ((off >> 3) & 0x70); }

// idesc: dtype=F32, a/btype=BF16, N=64, M=128
#define IDESC_128x64 0x8100490u

// ===========================================================================
// Mask dtype detection (bool serialized as int32/f32/bf16/u8)
// ===========================================================================
__global__ void detect_mask_kernel(const unsigned int* __restrict__ m, int nwords) {
    int flags = 0;
    for (int i = threadIdx.x + blockIdx.x * blockDim.x; i < nwords; i += blockDim.x * gridDim.x) {
        unsigned int w = m[i];
        if (w > 1u) flags |= 1;
        if (w != 0u && w != 0x3F800000u) flags |= 2;
        unsigned int lo = w & 0xFFFFu, hi = w >> 16;
        if ((lo != 0u && lo != 0x3F80u) || (hi != 0u && hi != 0x3F80u)) flags |= 4;
    }
    if (flags) atomicOr(&g_mask_flags, flags);
}

__device__ __forceinline__ int mask_read(const void* m, long i, int mode) {
    switch (mode) {
        case 0:  return ((const int*)m)[i] != 0;
        case 1:  return ((const float*)m)[i] != 0.0f;
        case 2:  return ((const unsigned short*)m)[i] != 0;
        default: return ((const unsigned char*)m)[i] != 0;
    }
}

__global__ void zero_out_kernel(float* __restrict__ out, int n) {
    int i = threadIdx.x + blockIdx.x * blockDim.x;
    if (i < n) out[i] = 0.0f;
}

// ===========================================================================
// Projection GEMMs: C = X @ W^T   (transposed smem tiles: conflict-free)
// ===========================================================================
__global__ __launch_bounds__(256) void proj_kernel(
    const float* __restrict__ a_z, const float* __restrict__ bv_z,
    const float* __restrict__ Wq, const float* __restrict__ Wk,
    const float* __restrict__ Wv, int Na, int Nb)
{
    __shared__ float As[16][68];   // [k][m]
    __shared__ float Bs[16][68];   // [k][n]

    int sel = blockIdx.z;
    const float* X = (sel == 0) ? a_z : bv_z;
    const float* W = (sel == 0) ? Wq : (sel == 1 ? Wk : Wv);
    float*       C = (sel == 0) ? g_Q : (sel == 1 ? g_K : g_V);
    int M = (sel == 0) ? Na : Nb;

    int mbase = blockIdx.x * 64;
    int nbase = blockIdx.y * 64;
    if (mbase >= M) return;

    int t  = threadIdx.x;
    int tm = t >> 4, tn = t & 15;
    int lm = t >> 2, lk = (t & 3) * 4;   // loader mapping: 64 m-rows x 4 float4

    float acc[4][4] = {};

    for (int kb = 0; kb < DIM; kb += 16) {
        int gm = mbase + lm;
        float4 xv = make_float4(0.f, 0.f, 0.f, 0.f);
        if (gm < M) xv = *(const float4*)&X[(long)gm * DIM + kb + lk];
        float4 wv = *(const float4*)&W[(long)(nbase + lm) * DIM + kb + lk];
        As[lk + 0][lm] = san(xv.x); As[lk + 1][lm] = san(xv.y);
        As[lk + 2][lm] = san(xv.z); As[lk + 3][lm] = san(xv.w);
        Bs[lk + 0][lm] = wv.x; Bs[lk + 1][lm] = wv.y;
        Bs[lk + 2][lm] = wv.z; Bs[lk + 3][lm] = wv.w;
        __syncthreads();
        #pragma unroll
        for (int k = 0; k < 16; k++) {
            float4 a4 = *(const float4*)&As[k][tm * 4];
            float4 b4 = *(const float4*)&Bs[k][tn * 4];
            const float* af = (const float*)&a4;
            const float* bf = (const float*)&b4;
            #pragma unroll
            for (int i = 0; i < 4; i++)
                #pragma unroll
                for (int j = 0; j < 4; j++) acc[i][j] += af[i] * bf[j];
        }
        __syncthreads();
    }
    #pragma unroll
    for (int i = 0; i < 4; i++) {
        int gm = mbase + tm * 4 + i;
        if (gm < M) {
            #pragma unroll
            for (int j = 0; j < 4; j++)
                C[(long)gm * DIM + nbase + tn * 4 + j] = acc[i][j];
        }
    }
}

// ===========================================================================
// Fused flash attention. Block = (a-tile of 128 rows) x (one head), 256 thr.
// sm_103a pass: tcgen05 bf16 hi/lo split SS MMAs.
// sm_103 pass:  register-tiled fp32 flash kernel (same launch signature).
// ===========================================================================
// SMEM byte offsets for tcgen05 path (operand tiles 1024-aligned)
#define SM_TMEMPTR 0
#define SM_MBARS   8
#define SM_MBARC   16
#define SM_QHI     1024
#define SM_QLO     (SM_QHI  + 16384)
#define SM_KHI     (SM_QLO  + 16384)
#define SM_KLO     (SM_KHI  + 8192)
#define SM_VTHI    (SM_KLO  + 8192)
#define SM_VTLO    (SM_VTHI + 8192)
#define SM_PHI     (SM_VTLO + 8192)
#define SM_PLO     (SM_PHI  + 16384)
#define SM_TOTAL   (SM_PLO  + 16384)   // 99328 bytes

#define TM_S   0     // S scores: 64 TMEM cols f32
#define TM_CTX 64    // context accumulator: 64 cols f32 (persistent)

__device__ __forceinline__ unsigned short bfu(float x) {
    return __bfloat16_as_ushort(__float2bfloat16_rn(x));
}
__device__ __forceinline__ float bff(unsigned short u) {
    return __bfloat162float(__ushort_as_bfloat16(u));
}

__device__ __forceinline__ void split_store8(char* smem, int hioff, int looff,
                                             uint32_t byteoff, float4 v) {
    unsigned short h0 = bfu(v.x), h1 = bfu(v.y), h2 = bfu(v.z), h3 = bfu(v.w);
    unsigned short l0 = bfu(v.x - bff(h0)), l1 = bfu(v.y - bff(h1));
    unsigned short l2 = bfu(v.z - bff(h2)), l3 = bfu(v.w - bff(h3));
    uint32_t sw = swz(byteoff);
    uint2 hv = make_uint2((uint32_t)h0 | ((uint32_t)h1 << 16),
                          (uint32_t)h2 | ((uint32_t)h3 << 16));
    uint2 lv = make_uint2((uint32_t)l0 | ((uint32_t)l1 << 16),
                          (uint32_t)l2 | ((uint32_t)l3 << 16));
    *(uint2*)(smem + hioff + sw) = hv;
    *(uint2*)(smem + looff + sw) = lv;
}

__global__ __launch_bounds__(256, 1) __cluster_dims__(1, 1, 1)
void attn_kernel(const void* __restrict__ mask, const float* __restrict__ weight,
                 float* __restrict__ out, int Na, int Nb)
{
#if TCGEN05_OK
    // =================== tcgen05 path (sm_103a cubin) =====================
    extern __shared__ char smem[];
    uint32_t sb = smem_u32(smem);
    int tid  = threadIdx.x;
    int wid  = tid >> 5;
    int lane = tid & 31;
    int abase = blockIdx.x * BM;
    int head  = blockIdx.y;
    int hoff  = head * DKH;
    int arow  = wid * 32 + lane;      // row owned by warps 0-3 in epilogue

    int fl = g_mask_flags;
    int mmode = (!(fl & 1)) ? 0 : (!(fl & 2)) ? 1 : (!(fl & 4)) ? 2 : 3;

    // TMEM alloc + mbarriers
    if (wid == 0) TC_ALLOC(sb + SM_TMEMPTR, 128);
    if (tid == 0) { MBAR_INIT(sb + SM_MBARS, 1); MBAR_INIT(sb + SM_MBARC, 1); }
    __syncthreads();
    uint32_t tmem;
    asm volatile("ld.shared.b32 %0, [%1];" : "=r"(tmem) : "r"(sb + SM_TMEMPTR));

    // Stage Q tile (128 x 64), hi/lo split, SW128 layout [a][c] (128B rows)
    for (int i = tid; i < BM * 16; i += 256) {
        int a = i >> 4, c4 = (i & 15) * 4;
        float4 q = *(const float4*)&g_Q[(long)(abase + a) * DIM + hoff + c4];
        split_store8(smem, SM_QHI, SM_QLO, (uint32_t)(a * 128 + c4 * 2), q);
    }
    __syncthreads();

    const uint64_t dQh = make_desc(sb + SM_QHI), dQl = make_desc(sb + SM_QLO);
    const uint64_t dKh = make_desc(sb + SM_KHI), dKl = make_desc(sb + SM_KLO);
    const uint64_t dVh = make_desc(sb + SM_VTHI), dVl = make_desc(sb + SM_VTLO);
    const uint64_t dPh = make_desc(sb + SM_PHI), dPl = make_desc(sb + SM_PLO);

    int phS = 0, phC = 0;
    float den = 0.0f;
    int t8 = tid - 128;
    const int NT = Nb / BN;

    for (int tile = 0; tile < NT; tile++) {
        int bt0 = tile * BN;

        // ---- issue gmem loads early (regs only; no smem hazard) ----
        float4 kreg[8], vreg[8];
        float bias[64];
        if (wid >= 4) {
            #pragma unroll
            for (int r = 0; r < 8; r++) {
                int i = t8 + r * 128;
                int b = i >> 4, c4 = (i & 15) * 4;
                kreg[r] = *(const float4*)&g_K[(long)(bt0 + b) * DIM + hoff + c4];
                vreg[r] = *(const float4*)&g_V[(long)(bt0 + b) * DIM + hoff + c4];
            }
        } else {
            long wb = (long)(abase + arow) * Nb + bt0;
            float4 wv[16];
            #pragma unroll
            for (int j = 0; j < 16; j++)
                wv[j] = *(const float4*)&weight[wb + j * 4];
            float msk[64];
            if (mmode <= 1) {
                const uint4* mp = (const uint4*)((const uint32_t*)mask + wb);
                #pragma unroll
                for (int j = 0; j < 16; j++) {
                    uint4 m4 = mp[j];
                    msk[j*4+0] = m4.x ? 0.f : -10000.f; msk[j*4+1] = m4.y ? 0.f : -10000.f;
                    msk[j*4+2] = m4.z ? 0.f : -10000.f; msk[j*4+3] = m4.w ? 0.f : -10000.f;
                }
            } else if (mmode == 2) {
                const uint4* mp = (const uint4*)((const unsigned short*)mask + wb);
                #pragma unroll
                for (int j = 0; j < 8; j++) {
                    uint4 m4 = mp[j];
                    uint32_t wds[4] = {m4.x, m4.y, m4.z, m4.w};
                    #pragma unroll
                    for (int q = 0; q < 4; q++) {
                        msk[j*8 + q*2 + 0] = (wds[q] & 0xFFFFu) ? 0.f : -10000.f;
                        msk[j*8 + q*2 + 1] = (wds[q] >> 16)     ? 0.f : -10000.f;
                    }
                }
            } else {
                const uint4* mp = (const uint4*)((const unsigned char*)mask + wb);
                #pragma unroll
                for (int j = 0; j < 4; j++) {
                    uint4 m4 = mp[j];
                    uint32_t wds[4] = {m4.x, m4.y, m4.z, m4.w};
                    #pragma unroll
                    for (int q = 0; q < 4; q++)
                        #pragma unroll
                        for (int bb = 0; bb < 4; bb++)
                            msk[j*16 + q*4 + bb] =
                                ((wds[q] >> (bb*8)) & 0xFFu) ? 0.f : -10000.f;
                }
            }
            #pragma unroll
            for (int c = 0; c < 64; c++)
                bias[c] = san(((const float*)wv)[c]) + msk[c];
        }

        // ---- wait prev PV done (frees K/V/P smem) ----
        if (tile > 0) { MBAR_WAIT(sb + SM_MBARC, phC); phC ^= 1; }

        // ---- stage K (row-major) and V^T (transposed) tiles ----
        if (wid >= 4) {
            #pragma unroll
            for (int r = 0; r < 8; r++) {
                int i = t8 + r * 128;
                int b = i >> 4, c4 = (i & 15) * 4;
                split_store8(smem, SM_KHI, SM_KLO, (uint32_t)(b * 128 + c4 * 2), kreg[r]);
                const float* vp = (const float*)&vreg[r];
                #pragma unroll
                for (int j = 0; j < 4; j++) {
                    int c = c4 + j;
                    unsigned short h = bfu(vp[j]);
                    unsigned short l = bfu(vp[j] - bff(h));
                    uint32_t off = swz((uint32_t)(c * 128 + b * 2));
                    *(unsigned short*)(smem + SM_VTHI + off) = h;
                    *(unsigned short*)(smem + SM_VTLO + off) = l;
                }
            }
        }
        FENCE_ASYNC_SHARED();
        __syncthreads();

        // ---- QK^T mma: S(128x64) += Qh*Kh + Qh*Kl + Ql*Kh ----
        if (wid == 0 && elect_one()) {
            uint64_t aset[3] = {dQh, dQh, dQl};
            uint64_t bset[3] = {dKh, dKl, dKh};
            #pragma unroll
            for (int s = 0; s < 3; s++)
                #pragma unroll
                for (int k = 0; k < 4; k++)
                    mma_bf16_ss(tmem + TM_S, aset[s] + k * 2, bset[s] + k * 2,
                                IDESC_128x64, !(s == 0 && k == 0));
            TC_COMMIT(sb + SM_MBARS);
        }
        MBAR_WAIT(sb + SM_MBARS, phS); phS ^= 1;
        TC_FENCE_AFTER();

        // ---- epilogue (warps 0-3): softmax terms -> P hi/lo in smem ----
        if (wid < 4) {
            #pragma unroll
            for (int hh = 0; hh < 2; hh++) {
                uint32_t dreg[32];
                TC_LD_X32(dreg, tmem + TM_S + hh * 32);
                TC_WAIT_LD();
                unsigned short hb[32], lb[32];
                #pragma unroll
                for (int cc = 0; cc < 32; cc++) {
                    int c = hh * 32 + cc;
                    float s = __uint_as_float(dreg[cc]);
                    float bv = bias[c];
                    float m01 = (bv > -5000.0f) ? 1.0f : 0.0f;
                    float att = s * 0.125f * m01 + bv;
                    att = fminf(fmaxf(att, -10.0f), 10.0f);
                    float e = __expf(att);
                    den += e;
                    unsigned short h = bfu(e);
                    hb[cc] = h;
                    lb[cc] = bfu(e - bff(h));
                }
                #pragma unroll
                for (int j = 0; j < 4; j++) {
                    uint4 hv, lv;
                    hv.x = (uint32_t)hb[j*8+0] | ((uint32_t)hb[j*8+1] << 16);
                    hv.y = (uint32_t)hb[j*8+2] | ((uint32_t)hb[j*8+3] << 16);
                    hv.z = (uint32_t)hb[j*8+4] | ((uint32_t)hb[j*8+5] << 16);
                    hv.w = (uint32_t)hb[j*8+6] | ((uint32_t)hb[j*8+7] << 16);
                    lv.x = (uint32_t)lb[j*8+0] | ((uint32_t)lb[j*8+1] << 16);
                    lv.y = (uint32_t)lb[j*8+2] | ((uint32_t)lb[j*8+3] << 16);
                    lv.z = (uint32_t)lb[j*8+4] | ((uint32_t)lb[j*8+5] << 16);
                    lv.w = (uint32_t)lb[j*8+6] | ((uint32_t)lb[j*8+7] << 16);
                    uint32_t off = swz((uint32_t)(arow * 128 + hh * 64 + j * 16));
                    *(uint4*)(smem + SM_PHI + off) = hv;
                    *(uint4*)(smem + SM_PLO + off) = lv;
                }
            }
        }
        FENCE_ASYNC_SHARED();
        __syncthreads();

        // ---- PV mma: CTX(128x64) += Ph*Vh + Ph*Vl + Pl*Vh (persistent) ----
        if (wid == 0 && elect_one()) {
            uint64_t aset[3] = {dPh, dPh, dPl};
            uint64_t bset[3] = {dVh, dVl, dVh};
            #pragma unroll
            for (int s = 0; s < 3; s++)
                #pragma unroll
                for (int k = 0; k < 4; k++)
                    mma_bf16_ss(tmem + TM_CTX, aset[s] + k * 2, bset[s] + k * 2,
                                IDESC_128x64, !(tile == 0 && s == 0 && k == 0));
            TC_COMMIT(sb + SM_MBARC);
        }
    }

    // ---- final: read context, normalize, cross-head mean via atomics ----
    MBAR_WAIT(sb + SM_MBARC, phC);
    TC_FENCE_AFTER();
    if (wid < 4) {
        float inv = 0.25f / den;
        #pragma unroll
        for (int hh = 0; hh < 2; hh++) {
            uint32_t creg[32];
            TC_LD_X32(creg, tmem + TM_CTX + hh * 32);
            TC_WAIT_LD();
            #pragma unroll
            for (int cc = 0; cc < 32; cc++)
                atomicAdd(&out[(long)(abase + arow) * DKH + hh * 32 + cc],
                          __uint_as_float(creg[cc]) * inv);
        }
        // influence = sum_b mean_h softmax = exactly 1 per row
        if (head == 0) out[(long)Na * DKH + abase + arow] = 1.0f;
    }
    TC_FENCE_BEFORE();
    __syncthreads();
    if (wid == 0) { TC_RELINQ(); TC_DEALLOC(tmem, 128); }

#else
    // ======== fp32 register-tiled fallback (plain sm_103 cubin) ===========
    // Layout (floats): Qs^T [64c][128a] @0 (8192) | KV [64][64] @8192 (4096,
    // K^T then V natural, time-shared) | E [64b][132] @12288 (8448) |
    // den[128] @20736.  Total 20864 floats = 83.5 KB <= SM_TOTAL.
    extern __shared__ float smf[];
    float* Qs  = smf;
    float* KV  = smf + 8192;
    float* Ef  = smf + 12288;
    float* dnf = smf + 20736;

    int tid   = threadIdx.x;
    int abase = blockIdx.x * BM;
    int head  = blockIdx.y;
    int hoff  = head * DKH;
    int agrp  = tid >> 3;     // 0..31 -> 4 a-rows each
    int bgrp  = tid & 7;      // 0..7  -> 8 b-cols (QK) / 8 dk-cols (PV)

    int fl = g_mask_flags;
    int mmode = (!(fl & 1)) ? 0 : (!(fl & 2)) ? 1 : (!(fl & 4)) ? 2 : 3;

    // Stage Q transposed: Qs[c][a]
    for (int i = tid; i < BM * 16; i += 256) {
        int a = i >> 4, c4 = (i & 15) * 4;
        float4 q = *(const float4*)&g_Q[(long)(abase + a) * DIM + hoff + c4];
        Qs[(c4 + 0) * 128 + a] = q.x;
        Qs[(c4 + 1) * 128 + a] = q.y;
        Qs[(c4 + 2) * 128 + a] = q.z;
        Qs[(c4 + 3) * 128 + a] = q.w;
    }

    float ctx[4][8] = {};    // [a][dk] persists across tiles
    float den4[4]   = {};    // per-a partial denominators

    for (int bt0 = 0; bt0 < Nb; bt0 += BN) {
        __syncthreads();   // protect KV (V) from previous PV readers

        // Stage K transposed: KV[c][b]
        for (int i = tid; i < BN * 16; i += 256) {
            int b = i >> 4, c4 = (i & 15) * 4;
            float4 kq = *(const float4*)&g_K[(long)(bt0 + b) * DIM + hoff + c4];
            KV[(c4 + 0) * 64 + b] = kq.x;
            KV[(c4 + 1) * 64 + b] = kq.y;
            KV[(c4 + 2) * 64 + b] = kq.z;
            KV[(c4 + 3) * 64 + b] = kq.w;
        }
        __syncthreads();

        // QK: s[4a][8b], conflict-free row-internal vector LDS
        float s[4][8] = {};
        #pragma unroll 8
        for (int k = 0; k < DKH; k++) {
            float4 qa = *(const float4*)&Qs[k * 128 + agrp * 4];
            float4 k0 = *(const float4*)&KV[k * 64 + bgrp * 8];
            float4 k1 = *(const float4*)&KV[k * 64 + bgrp * 8 + 4];
            const float* qf = (const float*)&qa;
            float kf[8];
            *(float4*)&kf[0] = k0; *(float4*)&kf[4] = k1;
            #pragma unroll
            for (int i = 0; i < 4; i++)
                #pragma unroll
                for (int j = 0; j < 8; j++) s[i][j] += qf[i] * kf[j];
        }

        // Epilogue: bias + clip + exp -> E[b][a] (stride 132)
        #pragma unroll
        for (int j = 0; j < 8; j++) {
            int b = bgrp * 8 + j;
            float4 ev;
            float* ep = (float*)&ev;
            #pragma unroll
            for (int i = 0; i < 4; i++) {
                long gi = (long)(abase + agrp * 4 + i) * Nb + (bt0 + b);
                float wv = san(weight[gi]);
                int m = mask_read(mask, gi, mmode);
                float att = s[i][j] * 0.125f * (m ? 1.0f : 0.0f) + wv
                            + (m ? 0.0f : -10000.0f);
                att = fminf(fmaxf(att, -10.0f), 10.0f);
                float e = __expf(att);
                den4[i] += e;
                ep[i] = e;
            }
            *(float4*)&Ef[b * 132 + agrp * 4] = ev;
        }
        __syncthreads();

        // Stage V natural [b][c] (overwrites K region)
        for (int i = tid; i < BN * 16; i += 256) {
            int b = i >> 4, c4 = (i & 15) * 4;
            *(float4*)&KV[b * 64 + c4] =
                *(const float4*)&g_V[(long)(bt0 + b) * DIM + hoff + c4];
        }
        __syncthreads();

        // PV: ctx[4a][8dk] += E[b][a] * V[b][dk]
        #pragma unroll 4
        for (int b = 0; b < BN; b++) {
            float4 ef = *(const float4*)&Ef[b * 132 + agrp * 4];
            float4 v0 = *(const float4*)&KV[b * 64 + bgrp * 8];
            float4 v1 = *(const float4*)&KV[b * 64 + bgrp * 8 + 4];
            const float* epf = (const float*)&ef;
            float vf[8];
            *(float4*)&vf[0] = v0; *(float4*)&vf[4] = v1;
            #pragma unroll
            for (int i = 0; i < 4; i++)
                #pragma unroll
                for (int j = 0; j < 8; j++) ctx[i][j] += epf[i] * vf[j];
        }
    }

    // Reduce den across the 8 bgrp lanes (consecutive within a warp)
    #pragma unroll
    for (int i = 0; i < 4; i++) {
        float v = den4[i];
        v += __shfl_xor_sync(0xffffffffu, v, 1);
        v += __shfl_xor_sync(0xffffffffu, v, 2);
        v += __shfl_xor_sync(0xffffffffu, v, 4);
        den4[i] = v;
    }
    if (bgrp == 0) {
        #pragma unroll
        for (int i = 0; i < 4; i++) dnf[agrp * 4 + i] = den4[i];
    }
    __syncthreads();

    // Normalize + cross-head mean via atomics
    #pragma unroll
    for (int i = 0; i < 4; i++) {
        int a = agrp * 4 + i;
        float inv = 0.25f / dnf[a];
        #pragma unroll
        for (int j = 0; j < 8; j++)
            atomicAdd(&out[(long)(abase + a) * DKH + bgrp * 8 + j],
                      ctx[i][j] * inv);
    }
    // influence = 1 exactly (softmax rows sum to 1)
    if (head == 0 && tid < BM) out[(long)Na * DKH + abase + tid] = 1.0f;
#endif
}

// ===========================================================================
extern "C" void kernel_launch(void* const* d_in, const int* in_sizes, int n_in,
                              void* d_out, int out_size)
{
    const float* a_z    = (const float*)d_in[0];
    const float* bv_z   = (const float*)d_in[1];
    const void*  mask   = d_in[2];
    const float* weight = (const float*)d_in[3];
    const float* Wq     = (const float*)d_in[4];
    const float* Wk     = (const float*)d_in[5];
    const float* Wv     = (const float*)d_in[6];

    int Na = in_sizes[0] / DIM;
    int Nb = in_sizes[1] / DIM;
    float* out = (float*)d_out;

    int nwords = in_sizes[2] / 4;
    if (nwords > 16384) nwords = 16384;
    detect_mask_kernel<<<32, 256>>>((const unsigned int*)mask, nwords);

    int Mmax = (Na > Nb) ? Na : Nb;
    dim3 pgrid((Mmax + 63) / 64, DIM / 64, 3);
    proj_kernel<<<pgrid, 256>>>(a_z, bv_z, Wq, Wk, Wv, Na, Nb);

    int nz = Na * DKH;
    zero_out_kernel<<<(nz + 255) / 256, 256>>>(out, nz);

    cudaFuncSetAttribute(attn_kernel,
                         cudaFuncAttributeMaxDynamicSharedMemorySize, SM_TOTAL);
    dim3 agrid(Na / BM, H);
    attn_kernel<<<agrid, 256, SM_TOTAL>>>(mask, weight, out, Na, Nb);
}